// round 8
// baseline (speedup 1.0000x reference)
#include <cuda_runtime.h>
#include <cstdint>
#include <math.h>

#define DB 32
#define DT 2048
#define DI 128
#define DH 256

// Scratch (allocation-free rule: __device__ globals), 256B-aligned for LDG/STG.128.
__device__ __align__(256) float g_xb[DB * DT * DH];
__device__ __align__(256) float g_hs[DB * DT * DH];

// ---------------- PTX helpers ----------------
__device__ __forceinline__ uint32_t smem_u32(const void* p) {
    return (uint32_t)__cvta_generic_to_shared(p);
}
__device__ __forceinline__ uint32_t mapa_u32(uint32_t a, uint32_t rank) {
    uint32_t r;
    asm volatile("mapa.shared::cluster.u32 %0, %1, %2;" : "=r"(r) : "r"(a), "r"(rank));
    return r;
}
__device__ __forceinline__ void mbar_init(uint32_t a, uint32_t cnt) {
    asm volatile("mbarrier.init.shared.b64 [%0], %1;" :: "r"(a), "r"(cnt) : "memory");
}
__device__ __forceinline__ void mbar_arrive_cluster(uint32_t a) {
    asm volatile("mbarrier.arrive.release.cluster.shared::cluster.b64 _, [%0];"
                 :: "r"(a) : "memory");
}
__device__ __forceinline__ void st_cluster_f32(uint32_t a, float v) {
    asm volatile("st.shared::cluster.f32 [%0], %1;" :: "r"(a), "f"(v) : "memory");
}
__device__ __forceinline__ void mbar_wait_parity(uint32_t a, uint32_t parity) {
    asm volatile(
        "{\n\t"
        ".reg .pred P;\n\t"
        "LWAIT_%=:\n\t"
        "mbarrier.try_wait.parity.acquire.cluster.shared.b64 P, [%0], %1;\n\t"
        "@!P bra LWAIT_%=;\n\t"
        "}" :: "r"(a), "r"(parity) : "memory");
}
__device__ __forceinline__ void cluster_arrive() {
    asm volatile("barrier.cluster.arrive.aligned;" ::: "memory");
}
__device__ __forceinline__ void cluster_wait() {
    asm volatile("barrier.cluster.wait.aligned;" ::: "memory");
}

// ---- packed f32x2 (sm_103a; PTX-only, ptxas won't auto-fuse) ----
__device__ __forceinline__ unsigned long long ffma2(unsigned long long a,
                                                    unsigned long long b,
                                                    unsigned long long c) {
    unsigned long long d;
    asm("fma.rn.f32x2 %0, %1, %2, %3;" : "=l"(d) : "l"(a), "l"(b), "l"(c));
    return d;
}
__device__ __forceinline__ unsigned long long pack2(float lo, float hi) {
    unsigned long long d;
    asm("mov.b64 %0, {%1, %2};" : "=l"(d) : "f"(lo), "f"(hi));
    return d;
}
__device__ __forceinline__ float2 unpack2(unsigned long long v) {
    float2 r;
    asm("mov.b64 {%0, %1}, %2;" : "=f"(r.x), "=f"(r.y) : "l"(v));
    return r;
}
__device__ __forceinline__ float tanh_fast(float x) {
    float r;
    asm("tanh.approx.f32 %0, %1;" : "=f"(r) : "f"(x));
    return r;
}

// ---------------- Tiled fp32 GEMM with f32x2: out[M,N] = in[M,K] @ W[K,N] ----
// BM=BN=64, BK=32, 256 threads, 4x4 microtile held as 8 packed f32x2 accums
// (pairs along m). B tile stored DUPLICATED in smem -> bdup pairs load directly
// as v2.u64, so the inner loop is 3 LDS.128 + 8 FFMA2 (vs 2 LDS + 16 FFMA).
template<int K_TOTAL>
__device__ __forceinline__ void gemm_body(const float* __restrict__ in,
                                          const float* __restrict__ W,
                                          float* __restrict__ out, int N)
{
    __shared__ __align__(16) float  sA[32][68];   // transposed: sA[k][m]
    __shared__ __align__(16) float2 sB2[32][64];  // duplicated: sB2[k][n] = (b,b)

    const int tx = threadIdx.x & 15;
    const int ty = threadIdx.x >> 4;
    const int mBase = blockIdx.y * 64;
    const int nBase = blockIdx.x * 64;

    unsigned long long acc[8];
    #pragma unroll
    for (int i = 0; i < 8; ++i) acc[i] = 0ull;     // (+0.f, +0.f)

    for (int k0 = 0; k0 < K_TOTAL; k0 += 32) {
        // A tile: 64m x 32k -> sA[k][m] (transposed). 512 float4, 2 iters.
        #pragma unroll
        for (int it = 0; it < 2; ++it) {
            int idx = threadIdx.x + it * 256;
            int m  = idx >> 3;                      // 8 float4 per m-row
            int kq = idx & 7;
            float4 v = *(const float4*)(in + (size_t)(mBase + m) * K_TOTAL + k0 + kq * 4);
            sA[kq * 4 + 0][m] = v.x;
            sA[kq * 4 + 1][m] = v.y;
            sA[kq * 4 + 2][m] = v.z;
            sA[kq * 4 + 3][m] = v.w;
        }
        // B tile: 32k x 64n, duplicated. 512 float4, 2 iters.
        #pragma unroll
        for (int it = 0; it < 2; ++it) {
            int idx = threadIdx.x + it * 256;
            int k  = idx >> 4;
            int nq = idx & 15;
            float4 v = *(const float4*)(W + (size_t)(k0 + k) * N + nBase + nq * 4);
            sB2[k][nq * 4 + 0] = make_float2(v.x, v.x);
            sB2[k][nq * 4 + 1] = make_float2(v.y, v.y);
            sB2[k][nq * 4 + 2] = make_float2(v.z, v.z);
            sB2[k][nq * 4 + 3] = make_float2(v.w, v.w);
        }
        __syncthreads();

        #pragma unroll 16
        for (int k = 0; k < 32; ++k) {
            ulonglong2 a2  = *(const ulonglong2*)(&sA[k][ty * 4]);     // (a0,a1),(a2,a3)
            ulonglong2 b01 = *(const ulonglong2*)(&sB2[k][tx * 4]);    // (b0,b0),(b1,b1)
            ulonglong2 b23 = *(const ulonglong2*)(&sB2[k][tx * 4 + 2]);// (b2,b2),(b3,b3)
            acc[0] = ffma2(a2.x, b01.x, acc[0]);
            acc[1] = ffma2(a2.x, b01.y, acc[1]);
            acc[2] = ffma2(a2.x, b23.x, acc[2]);
            acc[3] = ffma2(a2.x, b23.y, acc[3]);
            acc[4] = ffma2(a2.y, b01.x, acc[4]);
            acc[5] = ffma2(a2.y, b01.y, acc[5]);
            acc[6] = ffma2(a2.y, b23.x, acc[6]);
            acc[7] = ffma2(a2.y, b23.y, acc[7]);
        }
        __syncthreads();
    }

    // Epilogue: acc[j]   = rows (ty*4+0, ty*4+1) col j
    //           acc[4+j] = rows (ty*4+2, ty*4+3) col j
    float r[4][4];
    #pragma unroll
    for (int jj = 0; jj < 4; ++jj) {
        float2 u = unpack2(acc[jj]);
        float2 v = unpack2(acc[4 + jj]);
        r[0][jj] = u.x; r[1][jj] = u.y; r[2][jj] = v.x; r[3][jj] = v.y;
    }
    #pragma unroll
    for (int i = 0; i < 4; ++i) {
        float4 v = make_float4(r[i][0], r[i][1], r[i][2], r[i][3]);
        *(float4*)(out + (size_t)(mBase + ty * 4 + i) * N + nBase + tx * 4) = v;
    }
}

__global__ void __launch_bounds__(256, 2)
gemm_xb_kernel(const float* __restrict__ x, const float* __restrict__ Bm)
{
    gemm_body<DI>(x, Bm, g_xb, DH);          // [B*T,128] @ [128,256] -> g_xb
}

__global__ void __launch_bounds__(256, 2)
gemm_out_kernel(const float* __restrict__ C, float* __restrict__ out)
{
    gemm_body<DH>(g_hs, C, out, DH);         // [B*T,256] @ [256,256] -> out
}

// ---------------- Scan: one 4-CTA cluster per batch, mbarrier writer-push ----
// CTA rank r owns columns [64r, 64r+64); its 256x64 A-slice lives in registers
// as packed f32x2. Double-buffered h slots; per step:
//   wait full[s] (t>0) -> FMA partials -> STS part -> __syncthreads
//   -> tid<4: arrive empty[s] on all 4 CTAs (slot s consumed here)
//   -> tid<64: reduce + tanh.approx; wait empty[s^1] (t>0); push h_next into
//      all 4 CTAs' h_buf[s^1] (st.shared::cluster) + arrive their full[s^1].
// NO per-step cluster barrier (and no CCTL.IVALL L1 flush). Terminal
// barrier.cluster quiesces in-flight remote arrives before any CTA exits.
//
// Phases: full[s]  cnt=256 (64 producers x 4 source CTAs per fill)
//         empty[s] cnt=4   (1 elected arrive per CTA per consume)
// Producer skips the empty wait ONLY at t==0 (slot 1 never read before);
// no pre-arming (pre-arming empty[0] was the R2 phase-shift bug).
__global__ void __launch_bounds__(512, 1) __cluster_dims__(4, 1, 1)
scan_kernel(const float* __restrict__ A)
{
    __shared__ __align__(16) float h_buf[2][DH];
    __shared__ __align__(16) float part_t[64][8];     // [j][kc]
    __shared__ __align__(8)  unsigned long long mbars[4];

    const int tid = threadIdx.x;
    const int j   = tid & 63;
    const int kc  = tid >> 6;                 // 0..7
    uint32_t rank;
    asm("mov.u32 %0, %%cluster_ctarank;" : "=r"(rank));
    const int batch = blockIdx.x >> 2;
    const int colg  = (int)rank * 64 + j;

    const uint32_t mb = smem_u32(mbars);
    const uint32_t full_a[2]  = { mb,      mb + 8  };
    const uint32_t empty_a[2] = { mb + 16, mb + 24 };
    const uint32_t hb_a[2] = { smem_u32(&h_buf[0][0]), smem_u32(&h_buf[1][0]) };

    if (tid == 0) {
        mbar_init(full_a[0], 256);
        mbar_init(full_a[1], 256);
        mbar_init(empty_a[0], 4);
        mbar_init(empty_a[1], 4);
    }
    for (int i = tid; i < DH; i += 512) h_buf[0][i] = 0.f;   // h_0 = 0 in slot 0

    // A slice in registers, packed: a2[q] = (A[kc*32+2q][colg], A[kc*32+2q+1][colg])
    unsigned long long a2[16];
    #pragma unroll
    for (int q = 0; q < 16; ++q)
        a2[q] = pack2(A[(size_t)(kc * 32 + 2 * q)     * DH + colg],
                      A[(size_t)(kc * 32 + 2 * q + 1) * DH + colg]);

    // xb prefetch pipeline (depth 2), producers only
    const float* xb_b = g_xb + (size_t)batch * DT * DH + colg;
    float*       hs_b = g_hs + (size_t)batch * DT * DH + colg;
    float xb_buf[2] = {0.f, 0.f};
    if (tid < 64) {
        xb_buf[0] = __ldg(&xb_b[0]);
        xb_buf[1] = __ldg(&xb_b[(size_t)DH]);
    }

    __syncthreads();
    cluster_arrive(); cluster_wait();   // mbarriers + zeroed slot 0 visible cluster-wide

    unsigned pf[2] = {0, 0}, pe[2] = {0, 0};

    for (int t = 0; t < DT; ++t) {
        const int s = t & 1;

        if (t > 0) { mbar_wait_parity(full_a[s], pf[s]); pf[s] ^= 1; }

        // Partial dot over this thread's 32-k chunk (warp-uniform LDS.128 broadcast)
        {
            const ulonglong2* hb2 = (const ulonglong2*)(&h_buf[s][kc * 32]);
            unsigned long long acca = 0ull, accb = 0ull;
            #pragma unroll
            for (int i = 0; i < 8; ++i) {
                ulonglong2 hv = hb2[i];
                acca = ffma2(hv.x, a2[2 * i],     acca);
                accb = ffma2(hv.y, a2[2 * i + 1], accb);
            }
            float2 pa = unpack2(acca), pb = unpack2(accb);
            part_t[j][kc] = (pa.x + pa.y) + (pb.x + pb.y);
        }
        __syncthreads();                 // partials visible; h_buf[s] reads complete

        // Slot s consumed in this CTA -> tell all 4 producers' CTAs
        if (tid < 4)
            mbar_arrive_cluster(mapa_u32(empty_a[s], (uint32_t)tid));

        if (tid < 64) {
            float4 p0 = *(const float4*)(&part_t[j][0]);
            float4 p1 = *(const float4*)(&part_t[j][4]);
            float z = ((p0.x + p0.y) + (p0.z + p0.w))
                    + ((p1.x + p1.y) + (p1.z + p1.w)) + xb_buf[s];
            float hn = tanh_fast(z);
            hs_b[(size_t)t * DH] = hn;                 // fire-and-forget for phase 3

            if (t + 1 < DT) {
                const int w = s ^ 1;                   // slot being written
                if (t > 0) { mbar_wait_parity(empty_a[w], pe[w]); pe[w] ^= 1; }
                const uint32_t dst = hb_a[w] + (uint32_t)colg * 4;
                #pragma unroll
                for (uint32_t c = 0; c < 4; ++c)
                    st_cluster_f32(mapa_u32(dst, c), hn);
                #pragma unroll
                for (uint32_t c = 0; c < 4; ++c)
                    mbar_arrive_cluster(mapa_u32(full_a[w], c));
            }
            if (t + 2 < DT) xb_buf[s] = __ldg(&xb_b[(size_t)(t + 2) * DH]);
        }
    }

    // Quiesce: no CTA may exit while remote arrives targeting it are in flight.
    cluster_arrive(); cluster_wait();
}

// ---------------- Launch ----------------
extern "C" void kernel_launch(void* const* d_in, const int* in_sizes, int n_in,
                              void* d_out, int out_size)
{
    const float* x  = (const float*)d_in[0];   // [32,2048,128]
    const float* A  = (const float*)d_in[1];   // [256,256]
    const float* Bm = (const float*)d_in[2];   // [128,256]
    const float* C  = (const float*)d_in[3];   // [256,256]
    float* out = (float*)d_out;                // [32,2048,256]

    // Phase 1: xb = x @ Bm
    {
        dim3 grid(DH / 64, (DB * DT) / 64);    // (4, 1024)
        gemm_xb_kernel<<<grid, 256>>>(x, Bm);
    }
    // Phase 2: sequential scan, one 4-CTA cluster per batch (128 CTAs resident)
    {
        scan_kernel<<<DB * 4, 512>>>(A);
    }
    // Phase 3: out = hs @ C
    {
        dim3 grid(DH / 64, (DB * DT) / 64);
        gemm_out_kernel<<<grid, 256>>>(C, out);
    }
}

// round 10
// speedup vs baseline: 1.1219x; 1.1219x over previous
#include <cuda_runtime.h>
#include <cstdint>
#include <math.h>

#define DB 32
#define DT 2048
#define DI 128
#define DH 256

// Scratch (allocation-free rule: __device__ globals), 256B-aligned for LDG/STG.128.
__device__ __align__(256) float g_xb[DB * DT * DH];
__device__ __align__(256) float g_hs[DB * DT * DH];

// ---------------- PTX helpers ----------------
__device__ __forceinline__ uint32_t smem_u32(const void* p) {
    return (uint32_t)__cvta_generic_to_shared(p);
}
__device__ __forceinline__ uint32_t mapa_u32(uint32_t a, uint32_t rank) {
    uint32_t r;
    asm volatile("mapa.shared::cluster.u32 %0, %1, %2;" : "=r"(r) : "r"(a), "r"(rank));
    return r;
}
__device__ __forceinline__ void mbar_init(uint32_t a, uint32_t cnt) {
    asm volatile("mbarrier.init.shared.b64 [%0], %1;" :: "r"(a), "r"(cnt) : "memory");
}
__device__ __forceinline__ void mbar_arrive_cluster(uint32_t a) {
    asm volatile("mbarrier.arrive.release.cluster.shared::cluster.b64 _, [%0];"
                 :: "r"(a) : "memory");
}
__device__ __forceinline__ void st_cluster_f32(uint32_t a, float v) {
    asm volatile("st.shared::cluster.f32 [%0], %1;" :: "r"(a), "f"(v) : "memory");
}
// CTA-scope acquire wait (reference pattern: release.cluster arrive pairs with
// acquire.cta wait — the mbarrier flips only after the remote store landed in
// OUR smem). No cluster-scope fence => no CCTL.IVALL L1 flush in the loop.
__device__ __forceinline__ void mbar_wait_parity_cta(uint32_t a, uint32_t parity) {
    asm volatile(
        "{\n\t"
        ".reg .pred P;\n\t"
        "LWAIT_%=:\n\t"
        "mbarrier.try_wait.parity.acquire.cta.shared::cta.b64 P, [%0], %1;\n\t"
        "@!P bra LWAIT_%=;\n\t"
        "}" :: "r"(a), "r"(parity) : "memory");
}
__device__ __forceinline__ void cluster_arrive() {
    asm volatile("barrier.cluster.arrive.aligned;" ::: "memory");
}
__device__ __forceinline__ void cluster_wait() {
    asm volatile("barrier.cluster.wait.aligned;" ::: "memory");
}

// ---- packed f32x2 (scan dot only; kept out of the GEMMs after R8 regression) ----
__device__ __forceinline__ unsigned long long ffma2(unsigned long long a,
                                                    unsigned long long b,
                                                    unsigned long long c) {
    unsigned long long d;
    asm("fma.rn.f32x2 %0, %1, %2, %3;" : "=l"(d) : "l"(a), "l"(b), "l"(c));
    return d;
}
__device__ __forceinline__ unsigned long long pack2(float lo, float hi) {
    unsigned long long d;
    asm("mov.b64 %0, {%1, %2};" : "=l"(d) : "f"(lo), "f"(hi));
    return d;
}
__device__ __forceinline__ float2 unpack2(unsigned long long v) {
    float2 r;
    asm("mov.b64 {%0, %1}, %2;" : "=f"(r.x), "=f"(r.y) : "l"(v));
    return r;
}
__device__ __forceinline__ float tanh_fast(float x) {
    float r;
    asm("tanh.approx.f32 %0, %1;" : "=f"(r) : "f"(x));
    return r;
}

// ---------------- Tiled fp32 GEMM (R7 version, measured 131us for xb) ----------
// BM=BN=BK=64, 256 threads, 4x4 register microtile. K_TOTAL is also lda of `in`.
template<int K_TOTAL>
__device__ __forceinline__ void gemm_body(const float* __restrict__ in,
                                          const float* __restrict__ W,
                                          float* __restrict__ out, int N)
{
    __shared__ __align__(16) float sA[64][68];  // transposed: sA[k][m]
    __shared__ __align__(16) float sB[64][64];  // sB[k][n]

    const int tx = threadIdx.x & 15;
    const int ty = threadIdx.x >> 4;
    const int mBase = blockIdx.y * 64;
    const int nBase = blockIdx.x * 64;

    float acc[4][4] = {};

    for (int k0 = 0; k0 < K_TOTAL; k0 += 64) {
        #pragma unroll
        for (int it = 0; it < 4; ++it) {
            int idx = threadIdx.x + it * 256;
            int m  = idx >> 4;
            int kq = idx & 15;
            float4 v = *(const float4*)(in + (size_t)(mBase + m) * K_TOTAL + k0 + kq * 4);
            sA[kq * 4 + 0][m] = v.x;
            sA[kq * 4 + 1][m] = v.y;
            sA[kq * 4 + 2][m] = v.z;
            sA[kq * 4 + 3][m] = v.w;
        }
        #pragma unroll
        for (int it = 0; it < 4; ++it) {
            int idx = threadIdx.x + it * 256;
            int k  = idx >> 4;
            int nq = idx & 15;
            *(float4*)(&sB[k][nq * 4]) =
                *(const float4*)(W + (size_t)(k0 + k) * N + nBase + nq * 4);
        }
        __syncthreads();

        #pragma unroll 8
        for (int k = 0; k < 64; ++k) {
            float4 a4 = *(const float4*)(&sA[k][ty * 4]);
            float4 b4 = *(const float4*)(&sB[k][tx * 4]);
            float av[4] = {a4.x, a4.y, a4.z, a4.w};
            float bv[4] = {b4.x, b4.y, b4.z, b4.w};
            #pragma unroll
            for (int i = 0; i < 4; ++i)
                #pragma unroll
                for (int jj = 0; jj < 4; ++jj)
                    acc[i][jj] = fmaf(av[i], bv[jj], acc[i][jj]);
        }
        __syncthreads();
    }

    #pragma unroll
    for (int i = 0; i < 4; ++i) {
        float4 v = make_float4(acc[i][0], acc[i][1], acc[i][2], acc[i][3]);
        *(float4*)(out + (size_t)(mBase + ty * 4 + i) * N + nBase + tx * 4) = v;
    }
}

__global__ void __launch_bounds__(256, 2)
gemm_xb_kernel(const float* __restrict__ x, const float* __restrict__ Bm)
{
    gemm_body<DI>(x, Bm, g_xb, DH);          // [B*T,128] @ [128,256] -> g_xb
}

__global__ void __launch_bounds__(256, 2)
gemm_out_kernel(const float* __restrict__ C, float* __restrict__ out)
{
    gemm_body<DH>(g_hs, C, out, DH);         // [B*T,256] @ [256,256] -> out
}

// ---------------- Scan: one 4-CTA cluster per batch, mbarrier writer-push ----
// Protocol identical to R8 (correct) but ALL waits are acquire.cta (no
// cluster-scope fence / CCTL.IVALL in the loop — that was R8's 3900 cyc/step).
//   full[s]  cnt=256 : 64 producers x 4 source CTAs fill slot s
//   empty[s] cnt=4   : 1 elected arrive per CTA when slot s is consumed
// Producer skips the empty wait only at t==0 (slot 1 never read before).
// Terminal barrier.cluster quiesces in-flight remote arrives before exit.
__global__ void __launch_bounds__(512, 1) __cluster_dims__(4, 1, 1)
scan_kernel(const float* __restrict__ A)
{
    __shared__ __align__(16) float h_buf[2][DH];
    __shared__ __align__(16) float part[8][64];       // [kc][j] (conflict-free)
    __shared__ __align__(8)  unsigned long long mbars[4];

    const int tid = threadIdx.x;
    const int j   = tid & 63;
    const int kc  = tid >> 6;                 // 0..7
    uint32_t rank;
    asm("mov.u32 %0, %%cluster_ctarank;" : "=r"(rank));
    const int batch = blockIdx.x >> 2;
    const int colg  = (int)rank * 64 + j;

    const uint32_t mb = smem_u32(mbars);
    const uint32_t full_a[2]  = { mb,      mb + 8  };
    const uint32_t empty_a[2] = { mb + 16, mb + 24 };
    const uint32_t hb_a[2] = { smem_u32(&h_buf[0][0]), smem_u32(&h_buf[1][0]) };

    if (tid == 0) {
        mbar_init(full_a[0], 256);
        mbar_init(full_a[1], 256);
        mbar_init(empty_a[0], 4);
        mbar_init(empty_a[1], 4);
    }
    for (int i = tid; i < DH; i += 512) h_buf[0][i] = 0.f;   // h_0 = 0 in slot 0

    // A slice in registers, packed: a2[q] = (A[kc*32+2q][colg], A[kc*32+2q+1][colg])
    unsigned long long a2[16];
    #pragma unroll
    for (int q = 0; q < 16; ++q)
        a2[q] = pack2(A[(size_t)(kc * 32 + 2 * q)     * DH + colg],
                      A[(size_t)(kc * 32 + 2 * q + 1) * DH + colg]);

    // xb prefetch pipeline (depth 2), producers only
    const float* xb_b = g_xb + (size_t)batch * DT * DH + colg;
    float*       hs_b = g_hs + (size_t)batch * DT * DH + colg;
    float xb_buf[2] = {0.f, 0.f};
    if (tid < 64) {
        xb_buf[0] = __ldg(&xb_b[0]);
        xb_buf[1] = __ldg(&xb_b[(size_t)DH]);
    }

    __syncthreads();
    cluster_arrive(); cluster_wait();   // mbarriers + zeroed slot 0 visible cluster-wide

    unsigned pf[2] = {0, 0}, pe[2] = {0, 0};

    for (int t = 0; t < DT; ++t) {
        const int s = t & 1;

        if (t > 0) { mbar_wait_parity_cta(full_a[s], pf[s]); pf[s] ^= 1; }

        // Partial dot over this thread's 32-k chunk (warp-uniform LDS broadcast)
        {
            const ulonglong2* hb2 = (const ulonglong2*)(&h_buf[s][kc * 32]);
            unsigned long long acca = 0ull, accb = 0ull;
            #pragma unroll
            for (int i = 0; i < 8; ++i) {
                ulonglong2 hv = hb2[i];
                acca = ffma2(hv.x, a2[2 * i],     acca);
                accb = ffma2(hv.y, a2[2 * i + 1], accb);
            }
            float2 pa = unpack2(acca), pb = unpack2(accb);
            part[kc][j] = (pa.x + pa.y) + (pb.x + pb.y);
        }
        __syncthreads();                 // partials visible; h_buf[s] reads complete

        // Slot s consumed in this CTA -> tell all 4 CTAs' producers
        if (tid < 4)
            mbar_arrive_cluster(mapa_u32(empty_a[s], (uint32_t)tid));

        if (tid < 64) {
            float z = part[0][j] + part[1][j] + part[2][j] + part[3][j]
                    + part[4][j] + part[5][j] + part[6][j] + part[7][j]
                    + xb_buf[s];
            float hn = tanh_fast(z);
            hs_b[(size_t)t * DH] = hn;                 // fire-and-forget for phase 3

            if (t + 1 < DT) {
                const int w = s ^ 1;                   // slot being written
                if (t > 0) { mbar_wait_parity_cta(empty_a[w], pe[w]); pe[w] ^= 1; }
                const uint32_t dst = hb_a[w] + (uint32_t)colg * 4;
                #pragma unroll
                for (uint32_t c = 0; c < 4; ++c)
                    st_cluster_f32(mapa_u32(dst, c), hn);
                #pragma unroll
                for (uint32_t c = 0; c < 4; ++c)
                    mbar_arrive_cluster(mapa_u32(full_a[w], c));
            }
            if (t + 2 < DT) xb_buf[s] = __ldg(&xb_b[(size_t)(t + 2) * DH]);
        }
    }

    // Quiesce: no CTA may exit while remote arrives targeting it are in flight.
    cluster_arrive(); cluster_wait();
}

// ---------------- Launch ----------------
extern "C" void kernel_launch(void* const* d_in, const int* in_sizes, int n_in,
                              void* d_out, int out_size)
{
    const float* x  = (const float*)d_in[0];   // [32,2048,128]
    const float* A  = (const float*)d_in[1];   // [256,256]
    const float* Bm = (const float*)d_in[2];   // [128,256]
    const float* C  = (const float*)d_in[3];   // [256,256]
    float* out = (float*)d_out;                // [32,2048,256]

    // Phase 1: xb = x @ Bm
    {
        dim3 grid(DH / 64, (DB * DT) / 64);    // (4, 1024)
        gemm_xb_kernel<<<grid, 256>>>(x, Bm);
    }
    // Phase 2: sequential scan, one 4-CTA cluster per batch (128 CTAs resident)
    {
        scan_kernel<<<DB * 4, 512>>>(A);
    }
    // Phase 3: out = hs @ C
    {
        dim3 grid(DH / 64, (DB * DT) / 64);
        gemm_out_kernel<<<grid, 256>>>(C, out);
    }
}

// round 12
// speedup vs baseline: 1.8068x; 1.6105x over previous
#include <cuda_runtime.h>
#include <cstdint>
#include <math.h>

#define DB 32
#define DT 2048
#define DI 128
#define DH 256

// Scratch (allocation-free rule: __device__ globals), 256B-aligned for LDG/STG.128.
__device__ __align__(256) float g_xb[DB * DT * DH];
__device__ __align__(256) float g_hs[DB * DT * DH];

// ---------------- PTX helpers ----------------
__device__ __forceinline__ uint32_t smem_u32(const void* p) {
    return (uint32_t)__cvta_generic_to_shared(p);
}
__device__ __forceinline__ uint32_t mapa_u32(uint32_t a, uint32_t rank) {
    uint32_t r;
    asm volatile("mapa.shared::cluster.u32 %0, %1, %2;" : "=r"(r) : "r"(a), "r"(rank));
    return r;
}
__device__ __forceinline__ void mbar_init(uint32_t a, uint32_t cnt) {
    asm volatile("mbarrier.init.shared.b64 [%0], %1;" :: "r"(a), "r"(cnt) : "memory");
}
__device__ __forceinline__ void mbar_arrive_cluster(uint32_t a) {
    asm volatile("mbarrier.arrive.release.cluster.shared::cluster.b64 _, [%0];"
                 :: "r"(a) : "memory");
}
__device__ __forceinline__ void st_cluster_v4(uint32_t a, float4 v) {
    asm volatile("st.shared::cluster.v4.f32 [%0], {%1, %2, %3, %4};"
                 :: "r"(a), "f"(v.x), "f"(v.y), "f"(v.z), "f"(v.w) : "memory");
}
// CTA-scope acquire wait WITH suspend hint (reference macro form). The data
// pushed by peers lands in OUR smem before their release-arrive flips the
// count, so cta-scope acquire suffices; the hint avoids hot-spinning on the
// same SMEM line the remote arrives must update.
__device__ __forceinline__ void mbar_wait_parity_cta(uint32_t a, uint32_t parity) {
    asm volatile(
        "{\n\t"
        ".reg .pred P;\n\t"
        "LWAIT_%=:\n\t"
        "mbarrier.try_wait.parity.acquire.cta.shared::cta.b64 P, [%0], %1, 0x989680;\n\t"
        "@!P bra LWAIT_%=;\n\t"
        "}" :: "r"(a), "r"(parity) : "memory");
}
__device__ __forceinline__ void cluster_arrive() {
    asm volatile("barrier.cluster.arrive.aligned;" ::: "memory");
}
__device__ __forceinline__ void cluster_wait() {
    asm volatile("barrier.cluster.wait.aligned;" ::: "memory");
}

// ---- packed f32x2 (scan dot only; R8 showed it hurts the GEMM codegen) ----
__device__ __forceinline__ unsigned long long ffma2(unsigned long long a,
                                                    unsigned long long b,
                                                    unsigned long long c) {
    unsigned long long d;
    asm("fma.rn.f32x2 %0, %1, %2, %3;" : "=l"(d) : "l"(a), "l"(b), "l"(c));
    return d;
}
__device__ __forceinline__ unsigned long long pack2(float lo, float hi) {
    unsigned long long d;
    asm("mov.b64 %0, {%1, %2};" : "=l"(d) : "f"(lo), "f"(hi));
    return d;
}
__device__ __forceinline__ float2 unpack2(unsigned long long v) {
    float2 r;
    asm("mov.b64 {%0, %1}, %2;" : "=f"(r.x), "=f"(r.y) : "l"(v));
    return r;
}
__device__ __forceinline__ float tanh_fast(float x) {
    float r;
    asm("tanh.approx.f32 %0, %1;" : "=f"(r) : "f"(x));
    return r;
}

// ---------------- Tiled fp32 GEMM (R7 version, measured 131us for xb) ----------
template<int K_TOTAL>
__device__ __forceinline__ void gemm_body(const float* __restrict__ in,
                                          const float* __restrict__ W,
                                          float* __restrict__ out, int N)
{
    __shared__ __align__(16) float sA[64][68];  // transposed: sA[k][m]
    __shared__ __align__(16) float sB[64][64];  // sB[k][n]

    const int tx = threadIdx.x & 15;
    const int ty = threadIdx.x >> 4;
    const int mBase = blockIdx.y * 64;
    const int nBase = blockIdx.x * 64;

    float acc[4][4] = {};

    for (int k0 = 0; k0 < K_TOTAL; k0 += 64) {
        #pragma unroll
        for (int it = 0; it < 4; ++it) {
            int idx = threadIdx.x + it * 256;
            int m  = idx >> 4;
            int kq = idx & 15;
            float4 v = *(const float4*)(in + (size_t)(mBase + m) * K_TOTAL + k0 + kq * 4);
            sA[kq * 4 + 0][m] = v.x;
            sA[kq * 4 + 1][m] = v.y;
            sA[kq * 4 + 2][m] = v.z;
            sA[kq * 4 + 3][m] = v.w;
        }
        #pragma unroll
        for (int it = 0; it < 4; ++it) {
            int idx = threadIdx.x + it * 256;
            int k  = idx >> 4;
            int nq = idx & 15;
            *(float4*)(&sB[k][nq * 4]) =
                *(const float4*)(W + (size_t)(k0 + k) * N + nBase + nq * 4);
        }
        __syncthreads();

        #pragma unroll 8
        for (int k = 0; k < 64; ++k) {
            float4 a4 = *(const float4*)(&sA[k][ty * 4]);
            float4 b4 = *(const float4*)(&sB[k][tx * 4]);
            float av[4] = {a4.x, a4.y, a4.z, a4.w};
            float bv[4] = {b4.x, b4.y, b4.z, b4.w};
            #pragma unroll
            for (int i = 0; i < 4; ++i)
                #pragma unroll
                for (int jj = 0; jj < 4; ++jj)
                    acc[i][jj] = fmaf(av[i], bv[jj], acc[i][jj]);
        }
        __syncthreads();
    }

    #pragma unroll
    for (int i = 0; i < 4; ++i) {
        float4 v = make_float4(acc[i][0], acc[i][1], acc[i][2], acc[i][3]);
        *(float4*)(out + (size_t)(mBase + ty * 4 + i) * N + nBase + tx * 4) = v;
    }
}

__global__ void __launch_bounds__(256, 2)
gemm_xb_kernel(const float* __restrict__ x, const float* __restrict__ Bm)
{
    gemm_body<DI>(x, Bm, g_xb, DH);          // [B*T,128] @ [128,256] -> g_xb
}

__global__ void __launch_bounds__(256, 2)
gemm_out_kernel(const float* __restrict__ C, float* __restrict__ out)
{
    gemm_body<DH>(g_hs, C, out, DH);         // [B*T,256] @ [256,256] -> out
}

// ---------------- Scan: 4-CTA cluster / batch, relay-push, full-barrier only --
// Per step t (slot s = t&1, write slot w = s^1):
//   all 512: wait full[s] (t>0, suspend-hint) -> partial dot (f32x2, reg A)
//            -> STS part -> __syncthreads
//   tid<64 (producers): reduce 8 partials + xb -> tanh.approx -> STS stage[j]
//            -> STG hs -> bar.sync(1,64)
//            relay role: r=tid, dest CTA c=r&3, chunk i=r>>2:
//            ONE st.shared::cluster.v4.f32 of stage[4i..4i+3] into CTA c's
//            h_buf[w][rank*64+4i] + ONE release-arrive on CTA c's full[w].
// full[s] count = 64 (16 relays x 4 source CTAs). NO empty barrier: with 2
// slots, backpressure is transitive through the full chain (peer's slot-w
// reads at t-1 precede its __syncthreads, which precede its arrives for
// step t, which precede our full[s] wait at t, which precedes our writes
// into slot w). WAR is real-time-ordered; no extra fence needed.
__global__ void __launch_bounds__(512, 1) __cluster_dims__(4, 1, 1)
scan_kernel(const float* __restrict__ A)
{
    __shared__ __align__(16) float h_buf[2][DH];
    __shared__ __align__(16) float part[8][64];       // [kc][j]
    __shared__ __align__(16) float stage[64];         // producer staging
    __shared__ __align__(8)  unsigned long long mbars[2];

    const int tid = threadIdx.x;
    const int j   = tid & 63;
    const int kc  = tid >> 6;                 // 0..7
    uint32_t rank;
    asm("mov.u32 %0, %%cluster_ctarank;" : "=r"(rank));
    const int batch = blockIdx.x >> 2;
    const int colg  = (int)rank * 64 + j;

    const uint32_t mb = smem_u32(mbars);
    const uint32_t full_a[2] = { mb, mb + 8 };
    const uint32_t hb_a[2] = { smem_u32(&h_buf[0][0]), smem_u32(&h_buf[1][0]) };

    if (tid == 0) {
        mbar_init(full_a[0], 64);
        mbar_init(full_a[1], 64);
    }
    for (int i = tid; i < DH; i += 512) h_buf[0][i] = 0.f;   // h_0 = 0 (local copy)

    // A slice in registers, packed: a2[q] = (A[kc*32+2q][colg], A[kc*32+2q+1][colg])
    unsigned long long a2[16];
    #pragma unroll
    for (int q = 0; q < 16; ++q)
        a2[q] = pack2(A[(size_t)(kc * 32 + 2 * q)     * DH + colg],
                      A[(size_t)(kc * 32 + 2 * q + 1) * DH + colg]);

    // xb prefetch pipeline (depth 2), producers only
    const float* xb_b = g_xb + (size_t)batch * DT * DH + colg;
    float*       hs_b = g_hs + (size_t)batch * DT * DH + colg;
    float xb_buf[2] = {0.f, 0.f};
    if (tid < 64) {
        xb_buf[0] = __ldg(&xb_b[0]);
        xb_buf[1] = __ldg(&xb_b[(size_t)DH]);
    }

    // Relay assignment (producers double as relays)
    const uint32_t dest_c  = (uint32_t)(tid & 3);
    const int      chunk_i = (tid & 63) >> 2;          // 0..15

    __syncthreads();
    cluster_arrive(); cluster_wait();   // mbarriers + zeroed slot 0 visible cluster-wide

    unsigned pf[2] = {0, 0};

    for (int t = 0; t < DT; ++t) {
        const int s = t & 1;

        if (t > 0) { mbar_wait_parity_cta(full_a[s], pf[s]); pf[s] ^= 1; }

        // Partial dot over this thread's 32-k chunk (warp-uniform LDS broadcast)
        {
            const ulonglong2* hb2 = (const ulonglong2*)(&h_buf[s][kc * 32]);
            unsigned long long acca = 0ull, accb = 0ull;
            #pragma unroll
            for (int i = 0; i < 8; ++i) {
                ulonglong2 hv = hb2[i];
                acca = ffma2(hv.x, a2[2 * i],     acca);
                accb = ffma2(hv.y, a2[2 * i + 1], accb);
            }
            float2 pa = unpack2(acca), pb = unpack2(accb);
            part[kc][j] = (pa.x + pa.y) + (pb.x + pb.y);
        }
        __syncthreads();      // partials visible; h_buf[s] reads complete CTA-wide

        if (tid < 64) {
            float z = part[0][j] + part[1][j] + part[2][j] + part[3][j]
                    + part[4][j] + part[5][j] + part[6][j] + part[7][j]
                    + xb_buf[s];
            float hn = tanh_fast(z);
            stage[j] = hn;
            hs_b[(size_t)t * DH] = hn;                 // fire-and-forget for phase 3
            if (t + 2 < DT) xb_buf[s] = __ldg(&xb_b[(size_t)(t + 2) * DH]);

            asm volatile("bar.sync 1, 64;" ::: "memory");   // stage[] complete

            if (t + 1 < DT) {
                const int w = s ^ 1;
                float4 v = *(const float4*)(&stage[chunk_i * 4]);
                const uint32_t dst =
                    hb_a[w] + (uint32_t)((int)rank * 64 + chunk_i * 4) * 4;
                st_cluster_v4(mapa_u32(dst, dest_c), v);
                mbar_arrive_cluster(mapa_u32(full_a[w], dest_c));
            }
        }
    }

    // Quiesce before exit (cheap, once).
    cluster_arrive(); cluster_wait();
}

// ---------------- Launch ----------------
extern "C" void kernel_launch(void* const* d_in, const int* in_sizes, int n_in,
                              void* d_out, int out_size)
{
    const float* x  = (const float*)d_in[0];   // [32,2048,128]
    const float* A  = (const float*)d_in[1];   // [256,256]
    const float* Bm = (const float*)d_in[2];   // [128,256]
    const float* C  = (const float*)d_in[3];   // [256,256]
    float* out = (float*)d_out;                // [32,2048,256]

    // Phase 1: xb = x @ Bm
    {
        dim3 grid(DH / 64, (DB * DT) / 64);    // (4, 1024)
        gemm_xb_kernel<<<grid, 256>>>(x, Bm);
    }
    // Phase 2: sequential scan, one 4-CTA cluster per batch (128 CTAs resident)
    {
        scan_kernel<<<DB * 4, 512>>>(A);
    }
    // Phase 3: out = hs @ C
    {
        dim3 grid(DH / 64, (DB * DT) / 64);
        gemm_out_kernel<<<grid, 256>>>(C, out);
    }
}